// round 1
// baseline (speedup 1.0000x reference)
#include <cuda_runtime.h>
#include <cuda_fp16.h>
#include <cstdint>

#define N_TOK 8192
#define DDIM  2048
#define MDIM  512
#define NEXP  4
#define NP_MAX (N_TOK + NEXP*128)   // 8704 worst-case padded slots
#define NTILES (NP_MAX/128)         // 68

// ---------------- scratch (device globals; no allocation allowed) ----------------
__device__ int d_cnt[NEXP];
__device__ int d_cursor[NEXP];
__device__ int d_padoff[NEXP+1];
__device__ int d_tok[NP_MAX];
__device__ int d_is64;
__device__ __half d_x16[(size_t)NP_MAX*DDIM];        // gathered, expert-sorted x (fp16)
__device__ __half d_h16[(size_t)NP_MAX*MDIM];        // hidden activations (fp16)
__device__ __half d_w1h[(size_t)NEXP*MDIM*DDIM];     // W1 fp16
__device__ __half d_w2h[(size_t)NEXP*DDIM*MDIM];     // W2 fp16

__device__ __forceinline__ int get_dom(const void* dom, int n) {
    if (d_is64) return (int)((const long long*)dom)[n];
    return ((const int*)dom)[n];
}

// ---------------- setup kernels ----------------

// zero counters + detect domains dtype (int64 => all odd 32-bit words of first
// N words are zero; probability ~0 for random int32 values in [0,4))
__global__ void k_init(const unsigned* dom_words) {
    __shared__ int any;
    if (threadIdx.x == 0) any = 0;
    if (threadIdx.x < NEXP) { d_cnt[threadIdx.x] = 0; d_cursor[threadIdx.x] = 0; }
    __syncthreads();
    for (int i = 1 + 2*(int)threadIdx.x; i < N_TOK; i += 2*blockDim.x)
        if (dom_words[i] != 0) any = 1;   // benign race
    __syncthreads();
    if (threadIdx.x == 0) d_is64 = (any == 0) ? 1 : 0;
}

__global__ void k_count(const void* dom) {
    int n = blockIdx.x * blockDim.x + threadIdx.x;
    if (n < N_TOK) atomicAdd(&d_cnt[get_dom(dom, n)], 1);
}

__global__ void k_scan() {
    if (threadIdx.x == 0) {
        int off = 0;
        d_padoff[0] = 0;
        for (int e = 0; e < NEXP; e++) {
            off += (d_cnt[e] + 127) & ~127;   // pad each segment to 128 rows
            d_padoff[e+1] = off;
        }
    }
}

__global__ void k_fill() {
    int s = blockIdx.x * blockDim.x + threadIdx.x;
    if (s < NP_MAX) d_tok[s] = -1;
}

__global__ void k_perm(const void* dom) {
    int n = blockIdx.x * blockDim.x + threadIdx.x;
    if (n < N_TOK) {
        int e = get_dom(dom, n);
        int r = atomicAdd(&d_cursor[e], 1);
        d_tok[d_padoff[e] + r] = n;
    }
}

// convert both weight tensors to fp16 (vectorized by 4)
__global__ void k_convert_w(const float* __restrict__ W1, const float* __restrict__ W2) {
    size_t q = (size_t)blockIdx.x * blockDim.x + threadIdx.x;   // quad index
    size_t i = q * 4;
    float4 a = *(const float4*)(W1 + i);
    float4 b = *(const float4*)(W2 + i);
    __half2 a0 = __floats2half2_rn(a.x, a.y), a1 = __floats2half2_rn(a.z, a.w);
    __half2 b0 = __floats2half2_rn(b.x, b.y), b1 = __floats2half2_rn(b.z, b.w);
    *(__half2*)(d_w1h + i) = a0; *(__half2*)(d_w1h + i + 2) = a1;
    *(__half2*)(d_w2h + i) = b0; *(__half2*)(d_w2h + i + 2) = b1;
}

// gather x into expert-sorted fp16 buffer; zero padding rows
__global__ void k_gather(const float* __restrict__ x) {
    size_t q = (size_t)blockIdx.x * blockDim.x + threadIdx.x;  // NP_MAX*DDIM/4 quads
    int slot = (int)(q >> 9);                 // DDIM/4 = 512 quads per row
    int off  = ((int)q & 511) * 4;
    if (slot >= d_padoff[NEXP]) return;
    int tok = d_tok[slot];
    __half2 h0, h1;
    if (tok >= 0) {
        float4 v = *(const float4*)(x + (size_t)tok * DDIM + off);
        h0 = __floats2half2_rn(v.x, v.y);
        h1 = __floats2half2_rn(v.z, v.w);
    } else {
        h0 = __half2{__ushort_as_half(0), __ushort_as_half(0)};
        h1 = h0;
    }
    size_t o = (size_t)slot * DDIM + off;
    *(__half2*)(d_x16 + o) = h0;
    *(__half2*)(d_x16 + o + 2) = h1;
}

// ---------------- fp16 mma.sync GEMM ----------------
// C[slot, n] = sum_k A[slot,k] * B[e][n][k]   (both K-contiguous -> row.col mma)
// PHASE 0: A=d_x16 (K=2048), B=W1 (NOUT=512),  epilogue relu(acc+b1) -> d_h16
// PHASE 1: A=d_h16 (K=512),  B=W2 (NOUT=2048), epilogue x + acc + b2 -> out (scatter)

__device__ __forceinline__ void mma16816(float c[4], const unsigned a[4], const unsigned b[2]) {
    asm volatile(
        "mma.sync.aligned.m16n8k16.row.col.f32.f16.f16.f32 "
        "{%0,%1,%2,%3}, {%4,%5,%6,%7}, {%8,%9}, {%0,%1,%2,%3};\n"
        : "+f"(c[0]), "+f"(c[1]), "+f"(c[2]), "+f"(c[3])
        : "r"(a[0]), "r"(a[1]), "r"(a[2]), "r"(a[3]), "r"(b[0]), "r"(b[1]));
}

#define SM_STRIDE 40  // 32 + 8 halfs pad: verified conflict-free for the frag LDS pattern

template<int PHASE, int K, int NOUT>
__global__ __launch_bounds__(256)
void gemm_kernel(const float* __restrict__ bias,
                 const float* __restrict__ xres,
                 float* __restrict__ outf)
{
    const int mbase = blockIdx.x * 128;
    if (mbase >= d_padoff[NEXP]) return;
    int e = 0;
    while (e < NEXP-1 && mbase >= d_padoff[e+1]) e++;
    const int nbase = blockIdx.y * 64;

    const __half* __restrict__ A = (PHASE == 0) ? d_x16 : d_h16;
    const __half* __restrict__ B = (PHASE == 0) ? d_w1h : d_w2h;
    const __half* Ablk = A + (size_t)mbase * K;
    const __half* Bblk = B + ((size_t)e * NOUT + nbase) * K;

    __shared__ __half As[2][128][SM_STRIDE];
    __shared__ __half Bs[2][64][SM_STRIDE];

    const int tid  = threadIdx.x;
    const int warp = tid >> 5, lane = tid & 31;
    const int wm = warp >> 1, wn = warp & 1;       // 4 x 2 warps, each 32x32
    const int g = lane >> 2, qd = lane & 3;

    float acc[2][4][4];
    #pragma unroll
    for (int i = 0; i < 2; i++)
        #pragma unroll
        for (int j = 0; j < 4; j++)
            #pragma unroll
            for (int l = 0; l < 4; l++) acc[i][j][l] = 0.f;

    auto loadA = [&](int st, int k0) {
        #pragma unroll
        for (int i = 0; i < 2; i++) {
            int c = tid + i * 256;
            int row = c >> 2, ch = c & 3;
            const __half* src = Ablk + (size_t)row * K + k0 + ch * 8;
            unsigned dst = (unsigned)__cvta_generic_to_shared(&As[st][row][ch * 8]);
            asm volatile("cp.async.cg.shared.global [%0], [%1], 16;\n" :: "r"(dst), "l"(src) : "memory");
        }
    };
    auto loadB = [&](int st, int k0) {
        int row = tid >> 2, ch = tid & 3;  // 64 rows x 4 chunks = 256
        const __half* src = Bblk + (size_t)row * K + k0 + ch * 8;
        unsigned dst = (unsigned)__cvta_generic_to_shared(&Bs[st][row][ch * 8]);
        asm volatile("cp.async.cg.shared.global [%0], [%1], 16;\n" :: "r"(dst), "l"(src) : "memory");
    };

    constexpr int KT = K / 32;
    loadA(0, 0); loadB(0, 0);
    asm volatile("cp.async.commit_group;\n" ::: "memory");

    #pragma unroll 1
    for (int kt = 0; kt < KT; kt++) {
        asm volatile("cp.async.wait_group 0;\n" ::: "memory");
        __syncthreads();
        const int cur = kt & 1;
        if (kt + 1 < KT) {
            loadA(cur ^ 1, (kt + 1) * 32);
            loadB(cur ^ 1, (kt + 1) * 32);
            asm volatile("cp.async.commit_group;\n" ::: "memory");
        }
        #pragma unroll
        for (int ks = 0; ks < 2; ks++) {
            const int k0 = ks * 16;
            unsigned a[2][4], b[4][2];
            #pragma unroll
            for (int mi = 0; mi < 2; mi++) {
                int r0 = wm * 32 + mi * 16;
                a[mi][0] = *(const unsigned*)&As[cur][r0 + g    ][k0 + qd * 2];
                a[mi][1] = *(const unsigned*)&As[cur][r0 + g + 8][k0 + qd * 2];
                a[mi][2] = *(const unsigned*)&As[cur][r0 + g    ][k0 + qd * 2 + 8];
                a[mi][3] = *(const unsigned*)&As[cur][r0 + g + 8][k0 + qd * 2 + 8];
            }
            #pragma unroll
            for (int ni = 0; ni < 4; ni++) {
                int n0 = wn * 32 + ni * 8 + g;
                b[ni][0] = *(const unsigned*)&Bs[cur][n0][k0 + qd * 2];
                b[ni][1] = *(const unsigned*)&Bs[cur][n0][k0 + qd * 2 + 8];
            }
            #pragma unroll
            for (int mi = 0; mi < 2; mi++)
                #pragma unroll
                for (int ni = 0; ni < 4; ni++)
                    mma16816(acc[mi][ni], a[mi], b[ni]);
        }
        __syncthreads();
    }

    // ---------------- epilogue ----------------
    #pragma unroll
    for (int mi = 0; mi < 2; mi++) {
        #pragma unroll
        for (int hf = 0; hf < 2; hf++) {
            const int slot = mbase + wm * 32 + mi * 16 + g + hf * 8;
            if (PHASE == 1) {
                int tok = d_tok[slot];
                if (tok < 0) continue;
                #pragma unroll
                for (int ni = 0; ni < 4; ni++) {
                    int col = nbase + wn * 32 + ni * 8 + qd * 2;
                    size_t o = (size_t)tok * NOUT + col;
                    float v0 = acc[mi][ni][hf * 2 + 0] + bias[e * NOUT + col]     + xres[o];
                    float v1 = acc[mi][ni][hf * 2 + 1] + bias[e * NOUT + col + 1] + xres[o + 1];
                    float2 r; r.x = v0; r.y = v1;
                    *(float2*)(outf + o) = r;
                }
            } else {
                #pragma unroll
                for (int ni = 0; ni < 4; ni++) {
                    int col = nbase + wn * 32 + ni * 8 + qd * 2;
                    float v0 = acc[mi][ni][hf * 2 + 0] + bias[e * NOUT + col];
                    float v1 = acc[mi][ni][hf * 2 + 1] + bias[e * NOUT + col + 1];
                    v0 = fmaxf(v0, 0.f); v1 = fmaxf(v1, 0.f);
                    *(__half2*)(d_h16 + (size_t)slot * NOUT + col) = __floats2half2_rn(v0, v1);
                }
            }
        }
    }
}

// ---------------- launch ----------------
extern "C" void kernel_launch(void* const* d_in, const int* in_sizes, int n_in,
                              void* d_out, int out_size) {
    const float* x   = (const float*)d_in[0];
    const void*  dom = d_in[1];
    const float* W1  = (const float*)d_in[2];
    const float* b1  = (const float*)d_in[3];
    const float* W2  = (const float*)d_in[4];
    const float* b2  = (const float*)d_in[5];
    float* out = (float*)d_out;
    (void)in_sizes; (void)n_in; (void)out_size;

    k_init<<<1, 256>>>((const unsigned*)dom);
    k_count<<<N_TOK / 256, 256>>>(dom);
    k_scan<<<1, 32>>>();
    k_fill<<<(NP_MAX + 255) / 256, 256>>>();
    k_perm<<<N_TOK / 256, 256>>>(dom);
    k_convert_w<<<(NEXP * MDIM * DDIM / 4) / 256, 256>>>(W1, W2);
    k_gather<<<((size_t)NP_MAX * DDIM / 4) / 256, 256>>>(x);

    gemm_kernel<0, DDIM, MDIM><<<dim3(NTILES, MDIM / 64), 256>>>(b1, nullptr, nullptr);
    gemm_kernel<1, MDIM, DDIM><<<dim3(NTILES, DDIM / 64), 256>>>(b2, x, out);
}

// round 4
// speedup vs baseline: 1.3718x; 1.3718x over previous
#include <cuda_runtime.h>
#include <cuda_fp16.h>
#include <cstdint>

#define N_TOK 8192
#define DDIM  2048
#define MDIM  512
#define NEXP  4
#define NP_MAX (N_TOK + NEXP*128)   // 8704 worst-case padded slots
#define NTILES (NP_MAX/128)         // 68

// ---------------- scratch (device globals; no allocation allowed) ----------------
__device__ int d_cnt[NEXP];
__device__ int d_cursor[NEXP];
__device__ int d_padoff[NEXP+1];
__device__ int d_tok[NP_MAX];
__device__ int d_is64;
__device__ __half d_x16[(size_t)NP_MAX*DDIM];        // gathered, expert-sorted x (fp16)
__device__ __half d_h16[(size_t)NP_MAX*MDIM];        // hidden activations (fp16)
__device__ __half d_w1h[(size_t)NEXP*MDIM*DDIM];     // W1 fp16
__device__ __half d_w2h[(size_t)NEXP*DDIM*MDIM];     // W2 fp16

__device__ __forceinline__ int get_dom(const void* dom, int n) {
    if (d_is64) return (int)((const long long*)dom)[n];
    return ((const int*)dom)[n];
}

// ---------------- setup kernels ----------------
__global__ void k_init(const unsigned* dom_words) {
    __shared__ int any;
    if (threadIdx.x == 0) any = 0;
    if (threadIdx.x < NEXP) { d_cnt[threadIdx.x] = 0; d_cursor[threadIdx.x] = 0; }
    __syncthreads();
    for (int i = 1 + 2*(int)threadIdx.x; i < N_TOK; i += 2*blockDim.x)
        if (dom_words[i] != 0) any = 1;   // benign race
    __syncthreads();
    if (threadIdx.x == 0) d_is64 = (any == 0) ? 1 : 0;
}
__global__ void k_count(const void* dom) {
    int n = blockIdx.x * blockDim.x + threadIdx.x;
    if (n < N_TOK) atomicAdd(&d_cnt[get_dom(dom, n)], 1);
}
__global__ void k_scan() {
    if (threadIdx.x == 0) {
        int off = 0;
        d_padoff[0] = 0;
        for (int e = 0; e < NEXP; e++) {
            off += (d_cnt[e] + 127) & ~127;
            d_padoff[e+1] = off;
        }
    }
}
__global__ void k_fill() {
    int s = blockIdx.x * blockDim.x + threadIdx.x;
    if (s < NP_MAX) d_tok[s] = -1;
}
__global__ void k_perm(const void* dom) {
    int n = blockIdx.x * blockDim.x + threadIdx.x;
    if (n < N_TOK) {
        int e = get_dom(dom, n);
        int r = atomicAdd(&d_cursor[e], 1);
        d_tok[d_padoff[e] + r] = n;
    }
}
__global__ void k_convert_w(const float* __restrict__ W1, const float* __restrict__ W2) {
    size_t q = (size_t)blockIdx.x * blockDim.x + threadIdx.x;
    size_t i = q * 4;
    float4 a = *(const float4*)(W1 + i);
    float4 b = *(const float4*)(W2 + i);
    *(__half2*)(d_w1h + i)     = __floats2half2_rn(a.x, a.y);
    *(__half2*)(d_w1h + i + 2) = __floats2half2_rn(a.z, a.w);
    *(__half2*)(d_w2h + i)     = __floats2half2_rn(b.x, b.y);
    *(__half2*)(d_w2h + i + 2) = __floats2half2_rn(b.z, b.w);
}
__global__ void k_gather(const float* __restrict__ x) {
    size_t q = (size_t)blockIdx.x * blockDim.x + threadIdx.x;
    int slot = (int)(q >> 9);
    int off  = ((int)q & 511) * 4;
    if (slot >= d_padoff[NEXP]) return;
    int tok = d_tok[slot];
    __half2 h0, h1;
    if (tok >= 0) {
        float4 v = *(const float4*)(x + (size_t)tok * DDIM + off);
        h0 = __floats2half2_rn(v.x, v.y);
        h1 = __floats2half2_rn(v.z, v.w);
    } else {
        h0 = __half2{__ushort_as_half(0), __ushort_as_half(0)};
        h1 = h0;
    }
    size_t o = (size_t)slot * DDIM + off;
    *(__half2*)(d_x16 + o) = h0;
    *(__half2*)(d_x16 + o + 2) = h1;
}

// ---------------- HMMA (mma.sync) GEMM with ldmatrix + SW128 swizzle ----------------
// C[slot, n] = sum_k A[slot,k] * B[e][n][k]   (both K-contiguous -> row.col mma)
// PHASE0: A=d_x16 (K=2048), B=W1, NOUT=512  -> relu(acc+b1) -> d_h16 (fp16)
// PHASE1: A=d_h16 (K=512),  B=W2, NOUT=2048 -> x + acc + b2 -> out (scatter fp32)

__device__ __forceinline__ void mma16816(float* c, const unsigned* a, const unsigned* b) {
    asm volatile(
        "mma.sync.aligned.m16n8k16.row.col.f32.f16.f16.f32 "
        "{%0,%1,%2,%3}, {%4,%5,%6,%7}, {%8,%9}, {%0,%1,%2,%3};\n"
        : "+f"(c[0]), "+f"(c[1]), "+f"(c[2]), "+f"(c[3])
        : "r"(a[0]), "r"(a[1]), "r"(a[2]), "r"(a[3]), "r"(b[0]), "r"(b[1]));
}
__device__ __forceinline__ void ldsm4(unsigned* r, unsigned addr) {
    asm volatile("ldmatrix.sync.aligned.m8n8.x4.shared.b16 {%0,%1,%2,%3}, [%4];"
        : "=r"(r[0]), "=r"(r[1]), "=r"(r[2]), "=r"(r[3]) : "r"(addr));
}
__device__ __forceinline__ uint32_t smem_u32(const void* p) {
    uint32_t a;
    asm("{ .reg .u64 t; cvta.to.shared.u64 t, %1; cvt.u32.u64 %0, t; }" : "=r"(a) : "l"(p));
    return a;
}

// tile/pipeline config
#define GTM 128
#define GTN 128
#define GKC 64                         // halfs per K-chunk (128B rows)
#define GSTAGES 3
#define STAGE_BYTES (GTM*128)          // 16 KB (A or B, 128 rows x 128B)
#define GSMEM_TOTAL (GSTAGES*2*STAGE_BYTES)   // 96 KB

// swizzled byte offset within a stage: row in [0,128), unit = 16B chunk in [0,8)
__device__ __forceinline__ uint32_t swz(int row, int unit) {
    return (uint32_t)(row * 128 + ((unit ^ (row & 7)) * 16));
}

template<int PHASE, int K, int NOUT>
__global__ __launch_bounds__(256)
void gemm_hmma(const float* __restrict__ bias,
               const float* __restrict__ xres,
               float* __restrict__ outf)
{
    constexpr int NCH = K / GKC;

    extern __shared__ char smem[];
    const uint32_t sb = smem_u32(smem);

    const int tid = threadIdx.x, warp = tid >> 5, lane = tid & 31;
    const int wm = warp >> 1, wn = warp & 1;   // 4 warps in M, 2 in N; warp tile 32x64

    const int mbase = blockIdx.x * GTM;
    if (mbase >= d_padoff[NEXP]) return;
    int e = 0;
    while (e < NEXP-1 && mbase >= d_padoff[e+1]) e++;
    const int nbase = blockIdx.y * GTN;

    const __half* __restrict__ A = (PHASE == 0) ? d_x16 : d_h16;
    const __half* __restrict__ B = (PHASE == 0) ? d_w1h : d_w2h;
    const __half* Ab = A + (size_t)mbase * K;
    const __half* Bb = B + ((size_t)e * NOUT + nbase) * K;

    // per-thread cp.async assignment: 1024 units per tile, 256 threads -> 4 each
    auto load_chunk = [&](int i) {
        const int s = i % GSTAGES;
        const int k0 = i * GKC;
        const uint32_t abase = sb + s * STAGE_BYTES;
        const uint32_t bbase = sb + (GSTAGES + s) * STAGE_BYTES;
        #pragma unroll
        for (int it = 0; it < 4; it++) {
            int c = tid + it * 256;
            int row = c >> 3, u = c & 7;
            const void* srcA = Ab + (size_t)row * K + k0 + u * 8;
            const void* srcB = Bb + (size_t)row * K + k0 + u * 8;
            uint32_t o = swz(row, u);
            asm volatile("cp.async.cg.shared.global [%0], [%1], 16;\n" :: "r"(abase + o), "l"(srcA) : "memory");
            asm volatile("cp.async.cg.shared.global [%0], [%1], 16;\n" :: "r"(bbase + o), "l"(srcB) : "memory");
        }
    };

    float acc[2][8][4];
    #pragma unroll
    for (int i = 0; i < 2; i++)
        #pragma unroll
        for (int j = 0; j < 8; j++)
            #pragma unroll
            for (int l = 0; l < 4; l++) acc[i][j][l] = 0.f;

    #pragma unroll
    for (int i = 0; i < GSTAGES; i++) {
        if (i < NCH) load_chunk(i);
        asm volatile("cp.async.commit_group;\n" ::: "memory");
    }

    // ldmatrix lane address components (within a stage)
    const int aRowLo = wm * 32 + ((lane >> 3) & 1) * 8 + (lane & 7);  // + mi*16
    const int aUnitLo = (lane >> 4);                                   // + s*2
    const int bRowLo = wn * 64 + ((lane >> 4) << 3) + (lane & 7);      // + nf*16
    const int bUnitLo = ((lane >> 3) & 1);                             // + s*2

    #pragma unroll 1
    for (int i = 0; i < NCH; i++) {
        const int st = i % GSTAGES;
        asm volatile("cp.async.wait_group %0;\n" :: "n"(GSTAGES - 1) : "memory");
        __syncthreads();
        const uint32_t abase = sb + st * STAGE_BYTES;
        const uint32_t bbase = sb + (GSTAGES + st) * STAGE_BYTES;

        #pragma unroll
        for (int s = 0; s < 4; s++) {              // 4 k-steps of 16 per chunk
            unsigned a[2][4], b[4][4];
            #pragma unroll
            for (int mi = 0; mi < 2; mi++)
                ldsm4(a[mi], abase + swz(aRowLo + mi * 16, s * 2 + aUnitLo));
            #pragma unroll
            for (int nf = 0; nf < 4; nf++)
                ldsm4(b[nf], bbase + swz(bRowLo + nf * 16, s * 2 + bUnitLo));
            #pragma unroll
            for (int mi = 0; mi < 2; mi++)
                #pragma unroll
                for (int nf = 0; nf < 4; nf++) {
                    mma16816(acc[mi][nf*2+0], a[mi], &b[nf][0]);
                    mma16816(acc[mi][nf*2+1], a[mi], &b[nf][2]);
                }
        }
        __syncthreads();
        if (i + GSTAGES < NCH) load_chunk(i + GSTAGES);
        asm volatile("cp.async.commit_group;\n" ::: "memory");
    }

    // ---------------- epilogue ----------------
    const int g = lane >> 2, q = lane & 3;
    #pragma unroll
    for (int mi = 0; mi < 2; mi++) {
        #pragma unroll
        for (int hf = 0; hf < 2; hf++) {
            const int slot = mbase + wm * 32 + mi * 16 + hf * 8 + g;
            if (PHASE == 1) {
                const int tok = d_tok[slot];
                if (tok < 0) continue;
                #pragma unroll
                for (int ni = 0; ni < 8; ni++) {
                    const int col = nbase + wn * 64 + ni * 8 + q * 2;
                    const size_t o = (size_t)tok * NOUT + col;
                    float2 xr = *(const float2*)(xres + o);
                    float b0 = bias[e * NOUT + col], b1 = bias[e * NOUT + col + 1];
                    float2 r;
                    r.x = acc[mi][ni][hf*2+0] + b0 + xr.x;
                    r.y = acc[mi][ni][hf*2+1] + b1 + xr.y;
                    *(float2*)(outf + o) = r;
                }
            } else {
                #pragma unroll
                for (int ni = 0; ni < 8; ni++) {
                    const int col = nbase + wn * 64 + ni * 8 + q * 2;
                    float v0 = acc[mi][ni][hf*2+0] + bias[e * NOUT + col];
                    float v1 = acc[mi][ni][hf*2+1] + bias[e * NOUT + col + 1];
                    *(__half2*)(d_h16 + (size_t)slot * NOUT + col) =
                        __floats2half2_rn(fmaxf(v0, 0.f), fmaxf(v1, 0.f));
                }
            }
        }
    }
}

// ---------------- launch ----------------
extern "C" void kernel_launch(void* const* d_in, const int* in_sizes, int n_in,
                              void* d_out, int out_size) {
    const float* x   = (const float*)d_in[0];
    const void*  dom = d_in[1];
    const float* W1  = (const float*)d_in[2];
    const float* b1  = (const float*)d_in[3];
    const float* W2  = (const float*)d_in[4];
    const float* b2  = (const float*)d_in[5];
    float* out = (float*)d_out;
    (void)in_sizes; (void)n_in; (void)out_size;

    cudaFuncSetAttribute(gemm_hmma<0, DDIM, MDIM>,
                         cudaFuncAttributeMaxDynamicSharedMemorySize, GSMEM_TOTAL);
    cudaFuncSetAttribute(gemm_hmma<1, MDIM, DDIM>,
                         cudaFuncAttributeMaxDynamicSharedMemorySize, GSMEM_TOTAL);

    k_init<<<1, 256>>>((const unsigned*)dom);
    k_count<<<N_TOK / 256, 256>>>(dom);
    k_scan<<<1, 32>>>();
    k_fill<<<(NP_MAX + 255) / 256, 256>>>();
    k_perm<<<N_TOK / 256, 256>>>(dom);
    k_convert_w<<<(NEXP * MDIM * DDIM / 4) / 256, 256>>>(W1, W2);
    k_gather<<<((size_t)NP_MAX * DDIM / 4) / 256, 256>>>(x);

    gemm_hmma<0, DDIM, MDIM><<<dim3(NTILES, MDIM / GTN), 256, GSMEM_TOTAL>>>(b1, nullptr, nullptr);
    gemm_hmma<1, MDIM, DDIM><<<dim3(NTILES, DDIM / GTN), 256, GSMEM_TOTAL>>>(b2, x, out);
}